// round 5
// baseline (speedup 1.0000x reference)
#include <cuda_runtime.h>
#include <cuda_fp16.h>
#include <stdint.h>
#include <math.h>

// ---------------- problem constants ----------------
#define MDIM 131072   // B*N rows
#define KDIM 512      // D
#define NDIM 512      // H
#define NNODES 2048
#define HALFN 1024

#define TILE_M 128
#define TILE_N 128
#define KC 64
#define NCHUNK 8
#define THREADS 256
#define PITCH 144     // bytes per k-row in smem tiles (128 data + 16 pad)

// smem: 4 tiles per stage (A limb0/1, B limb0/1), 2 stages
#define A_OFF(s, p) ((((s) * 2) + (p)) * 18432)
#define B_OFF(s, p) (73728 + (((s) * 2) + (p)) * 18432)
#define SMEM_BYTES  (147456 + 128)
#define HPITCH 132            // floats, epilogue staging pitch
#define SCALE_UP 4096.0f
#define SCALE_DN (1.0f / 4096.0f)

// ---------------- device scratch ----------------
__device__ float  g_h[(size_t)MDIM * NDIM];        // 256 MB hidden
__device__ __half g_Xh[(size_t)MDIM * KDIM];       // x fp16 high limb [m][k]
__device__ __half g_Xm[(size_t)MDIM * KDIM];       // x fp16 low limb (x4096)
__device__ float  g_ps[2048 * NDIM];               // per-slab column sums
__device__ float  g_pq[2048 * NDIM];               // per-slab column sumsq
__device__ float  g_a[NDIM];
__device__ float  g_c[NDIM];
__device__ __half g_Bh[KDIM * NDIM];               // W1^T limbs, [n][k]
__device__ __half g_Bm[KDIM * NDIM];               // scaled by 4096

// ---------------- PTX helpers ----------------
__device__ __forceinline__ uint32_t smem_u32(const void* p) {
    uint32_t a;
    asm("{ .reg .u64 t; cvta.to.shared.u64 t, %1; cvt.u32.u64 %0, t; }" : "=r"(a) : "l"(p));
    return a;
}
#define LDS128(r0, r1, r2, r3, addr) \
    asm volatile("ld.shared.v4.b32 {%0, %1, %2, %3}, [%4];" \
                 : "=r"(r0), "=r"(r1), "=r"(r2), "=r"(r3) : "r"(addr))
#define LDS32(r0, addr) \
    asm volatile("ld.shared.b32 %0, [%1];" : "=r"(r0) : "r"(addr))
#define STS64F(addr, x, y) \
    asm volatile("st.shared.v2.f32 [%0], {%1, %2};" :: "r"(addr), "f"(x), "f"(y) : "memory")

__device__ __forceinline__ void ldsm_x4(uint32_t* r, uint32_t addr) {
    asm volatile("ldmatrix.sync.aligned.m8n8.x4.shared.b16 {%0,%1,%2,%3}, [%4];"
                 : "=r"(r[0]), "=r"(r[1]), "=r"(r[2]), "=r"(r[3]) : "r"(addr));
}
__device__ __forceinline__ void mma16816(float* d, const uint32_t* a, const uint32_t* b) {
    asm volatile(
        "mma.sync.aligned.m16n8k16.row.col.f32.f16.f16.f32 "
        "{%0,%1,%2,%3}, {%4,%5,%6,%7}, {%8,%9}, {%0,%1,%2,%3};"
        : "+f"(d[0]), "+f"(d[1]), "+f"(d[2]), "+f"(d[3])
        : "r"(a[0]), "r"(a[1]), "r"(a[2]), "r"(a[3]), "r"(b[0]), "r"(b[1]));
}
__device__ __forceinline__ void cpasync16(uint32_t dst, const void* src) {
    asm volatile("cp.async.cg.shared.global [%0], [%1], 16;" :: "r"(dst), "l"(src));
}
#define CP_COMMIT() asm volatile("cp.async.commit_group;" ::: "memory")
#define CP_WAIT0()  asm volatile("cp.async.wait_group 0;" ::: "memory")

// scaled fp16x2 split: v = h + m*2^-12 (m stored pre-scaled by 2^12)
__device__ __forceinline__ void split2(float v, uint32_t& h, uint32_t& m) {
    __half hh = __float2half_rn(v);
    float r = (v - __half2float(hh)) * SCALE_UP;
    __half hm = __float2half_rn(r);
    h = (uint32_t)__half_as_ushort(hh);
    m = (uint32_t)__half_as_ushort(hm);
}

// ---------------------------------------------------------------------------
// K1a: split x fp32 -> 2 fp16 matrices [m][k]
// ---------------------------------------------------------------------------
__global__ void __launch_bounds__(256) splitX_kernel(const float* __restrict__ X) {
    size_t i = (size_t)blockIdx.x * 256 + threadIdx.x;   // float4 index
    float4 v = ((const float4*)X)[i];
    uint32_t h0, m0v, h1, m1v, h2, m2v, h3, m3v;
    split2(v.x, h0, m0v);
    split2(v.y, h1, m1v);
    split2(v.z, h2, m2v);
    split2(v.w, h3, m3v);
    uint2 ph, pm;
    ph.x = h0 | (h1 << 16);  ph.y = h2 | (h3 << 16);
    pm.x = m0v | (m1v << 16); pm.y = m2v | (m3v << 16);
    ((uint2*)g_Xh)[i] = ph;
    ((uint2*)g_Xm)[i] = pm;
}

// ---------------------------------------------------------------------------
// K1b: split W1 [k][n] fp32 -> 2 fp16 matrices [n][k]
// ---------------------------------------------------------------------------
__global__ void __launch_bounds__(256) splitB_kernel(const float* __restrict__ W1) {
    int i = blockIdx.x * blockDim.x + threadIdx.x;   // i = k*512 + n
    int k = i >> 9, n = i & 511;
    uint32_t h, m;
    split2(W1[i], h, m);
    int o = n * KDIM + k;
    g_Bh[o] = __ushort_as_half((unsigned short)h);
    g_Bm[o] = __ushort_as_half((unsigned short)m);
}

// ---------------------------------------------------------------------------
// K2: fp16x2 HMMA GEMM  h = x @ W1 + b1, fused per-slab column stats
// ---------------------------------------------------------------------------
__device__ __forceinline__ void issue_loads(uint32_t base, int m0, int n0, int c, int tid) {
    const int s = c & 1;
    const int p = tid >> 7;          // limb
    const int r = tid & 127;         // row within tile
    const __half* xa = (p == 0) ? g_Xh : g_Xm;
    const __half* xb = (p == 0) ? g_Bh : g_Bm;
    const __half* srcA = xa + (size_t)(m0 + r) * KDIM + c * KC;
    const __half* srcB = xb + (size_t)(n0 + r) * KDIM + c * KC;
    uint32_t dstA = base + A_OFF(s, p) + r * PITCH;
    uint32_t dstB = base + B_OFF(s, p) + r * PITCH;
#pragma unroll
    for (int q = 0; q < 8; q++) cpasync16(dstA + q * 16, srcA + q * 8);
#pragma unroll
    for (int q = 0; q < 8; q++) cpasync16(dstB + q * 16, srcB + q * 8);
    CP_COMMIT();
}

__global__ void __launch_bounds__(THREADS, 1)
gemm_kernel(const float* __restrict__ b1) {
    extern __shared__ char dyn[];
    __shared__ float sbias[TILE_N];

    const uint32_t base = (smem_u32(dyn) + 127u) & ~127u;
    const int tid = threadIdx.x;
    const int wid = tid >> 5;
    const int lane = tid & 31;
    const int m0 = blockIdx.y * TILE_M;
    const int n0 = blockIdx.x * TILE_N;

    if (tid < TILE_N) sbias[tid] = b1[n0 + tid];

    const int wm = (wid & 3) * 32;     // warp m-offset
    const int wn = (wid >> 2) * 64;    // warp n-offset

    float a1[2][8][4], a2[2][8][4];
#pragma unroll
    for (int i = 0; i < 2; i++)
#pragma unroll
        for (int j = 0; j < 8; j++)
#pragma unroll
            for (int q = 0; q < 4; q++) { a1[i][j][q] = 0.f; a2[i][j][q] = 0.f; }

    // prologue
    issue_loads(base, m0, n0, 0, tid);
    CP_WAIT0();
    __syncthreads();

    // lane-constant address components
    const int arow = lane & 15;
    const int acolh = (lane >> 4) * 16;                      // bytes
    const int bm = lane >> 3;                                // matrix id 0..3
    const int brow = ((bm & 2) << 2) + (lane & 7);           // row within 16-row pair
    const int bko = (bm & 1) * 16;                           // k-half offset bytes

    for (int c = 0; c < NCHUNK; c++) {
        const int s = c & 1;
        if (c + 1 < NCHUNK) issue_loads(base, m0, n0, c + 1, tid);

#pragma unroll
        for (int k16 = 0; k16 < 4; k16++) {
            const uint32_t koA = (uint32_t)(k16 * 32 + acolh);
            const uint32_t koB = (uint32_t)(k16 * 32 + bko);
            uint32_t aH[2][4], aM[2][4];
#pragma unroll
            for (int i = 0; i < 2; i++) {
                uint32_t ra = (uint32_t)((wm + i * 16 + arow) * PITCH);
                ldsm_x4(aH[i], base + A_OFF(s, 0) + ra + koA);
                ldsm_x4(aM[i], base + A_OFF(s, 1) + ra + koA);
            }
#pragma unroll
            for (int jj = 0; jj < 4; jj++) {
                uint32_t rb = (uint32_t)((wn + jj * 16 + brow) * PITCH) + koB;
                uint32_t bh[4], bmr[4];
                ldsm_x4(bh, base + B_OFF(s, 0) + rb);
                ldsm_x4(bmr, base + B_OFF(s, 1) + rb);
                // H*H -> a1 ; M*H -> a2 ; H*M -> a2
#pragma unroll
                for (int i = 0; i < 2; i++) {
                    mma16816(a1[i][jj * 2 + 0], aH[i], bh + 0);
                    mma16816(a1[i][jj * 2 + 1], aH[i], bh + 2);
                    mma16816(a2[i][jj * 2 + 0], aM[i], bh + 0);
                    mma16816(a2[i][jj * 2 + 1], aM[i], bh + 2);
                    mma16816(a2[i][jj * 2 + 0], aH[i], bmr + 0);
                    mma16816(a2[i][jj * 2 + 1], aH[i], bmr + 2);
                }
            }
        }

        if (c + 1 < NCHUNK) CP_WAIT0();
        __syncthreads();
    }

    // ---------------- epilogue: combine + stage to smem ----------------
#pragma unroll
    for (int i = 0; i < 2; i++)
#pragma unroll
        for (int j = 0; j < 8; j++) {
            int r0 = wm + i * 16 + (lane >> 2);
            int c0 = wn + j * 8 + (lane & 3) * 2;
            float v0 = a1[i][j][0] + a2[i][j][0] * SCALE_DN;
            float v1 = a1[i][j][1] + a2[i][j][1] * SCALE_DN;
            float v2 = a1[i][j][2] + a2[i][j][2] * SCALE_DN;
            float v3 = a1[i][j][3] + a2[i][j][3] * SCALE_DN;
            STS64F(base + (uint32_t)((r0 * HPITCH + c0) * 4), v0, v1);
            STS64F(base + (uint32_t)(((r0 + 8) * HPITCH + c0) * 4), v2, v3);
        }
    __syncthreads();

    // coalesced global write with bias
#pragma unroll 4
    for (int t = 0; t < 16; t++) {
        int fidx = tid + t * 256;          // float4 index
        int r = fidx >> 5, cs = fidx & 31;
        uint32_t u0, u1, u2, u3;
        LDS128(u0, u1, u2, u3, base + (uint32_t)((r * HPITCH + cs * 4) * 4));
        float4 bv = *(const float4*)&sbias[cs * 4];
        float4 o;
        o.x = __uint_as_float(u0) + bv.x;
        o.y = __uint_as_float(u1) + bv.y;
        o.z = __uint_as_float(u2) + bv.z;
        o.w = __uint_as_float(u3) + bv.w;
        *(float4*)&g_h[(size_t)(m0 + r) * NDIM + n0 + cs * 4] = o;
    }

    // per-slab column stats (idempotent partials; 2 threads per column)
    {
        int col = tid & 127;
        int half = tid >> 7;
        float bcolv = sbias[col];
        float ss = 0.f, s2 = 0.f;
#pragma unroll 8
        for (int r = half * 64; r < half * 64 + 64; r++) {
            uint32_t u;
            LDS32(u, base + (uint32_t)((r * HPITCH + col) * 4));
            float v = __uint_as_float(u) + bcolv;
            ss += v;
            s2 = fmaf(v, v, s2);
        }
        int slot = (blockIdx.y * 2 + half) * NDIM + n0 + col;
        g_ps[slot] = ss;
        g_pq[slot] = s2;
    }
}

// ---------------------------------------------------------------------------
// K3: finalize BN affine (one warp per column, fp64 reduce of 2048 partials)
// ---------------------------------------------------------------------------
__global__ void __launch_bounds__(256) finalize_kernel(const float* __restrict__ gamma,
                                                       const float* __restrict__ beta) {
    int col = blockIdx.x * 8 + (threadIdx.x >> 5);
    int lane = threadIdx.x & 31;
    double s = 0.0, q = 0.0;
    for (int i = lane; i < 2048; i += 32) {
        s += (double)g_ps[i * NDIM + col];
        q += (double)g_pq[i * NDIM + col];
    }
#pragma unroll
    for (int off = 16; off > 0; off >>= 1) {
        s += __shfl_down_sync(0xFFFFFFFFu, s, off);
        q += __shfl_down_sync(0xFFFFFFFFu, q, off);
    }
    if (lane == 0) {
        double mu = s / (double)MDIM;
        double var = q / (double)MDIM - mu * mu;
        double a = (double)gamma[col] / sqrt(var + 1e-5);
        g_a[col] = (float)a;
        g_c[col] = (float)((double)beta[col] - mu * a);
    }
}

// ---------------------------------------------------------------------------
// K4: heads (one warp per row; W, a, c staged in shared)
// ---------------------------------------------------------------------------
__global__ void __launch_bounds__(256) heads_kernel(const float* __restrict__ Hbuf,
                                                    const float* __restrict__ Wa,
                                                    const float* __restrict__ ba,
                                                    const float* __restrict__ Wb,
                                                    const float* __restrict__ bb,
                                                    float* __restrict__ out) {
    __shared__ float sWa[512 * 4];     // padded [j][4]
    __shared__ float sWb[512 * 8];     // padded [j][8]
    __shared__ float sa[512], sc[512];

    const int tid = threadIdx.x;
    // cooperative staging
#pragma unroll
    for (int t = 0; t < 6; t++) {
        int i = tid + t * 256;         // 0..1535
        sWa[(i / 3) * 4 + (i % 3)] = Wa[i];
    }
#pragma unroll
    for (int t = 0; t < 10; t++) {
        int i = tid + t * 256;         // 0..2559
        sWb[(i / 5) * 8 + (i % 5)] = Wb[i];
    }
    {
        int i = tid * 2;
        sa[i] = g_a[i]; sa[i + 1] = g_a[i + 1];
        sc[i] = g_c[i]; sc[i + 1] = g_c[i + 1];
    }
    __syncthreads();

    const int row = (int)((blockIdx.x * blockDim.x + tid) >> 5);
    const int lane = tid & 31;
    const int n = row & (NNODES - 1);
    const bool isA = (n < HALFN);

    const float4* h4 = (const float4*)(Hbuf + (size_t)row * NDIM);
    const uint32_t sab = smem_u32(sa), scb = smem_u32(sc);
    const uint32_t swa = smem_u32(sWa), swb = smem_u32(sWb);

    float acc[5] = {0.f, 0.f, 0.f, 0.f, 0.f};

#pragma unroll
    for (int i = 0; i < 4; i++) {
        int j4 = i * 32 + lane;        // float4 index; columns 4*j4..4*j4+3
        float4 v = h4[j4];
        uint32_t a0, a1, a2, a3, c0, c1, c2, c3;
        LDS128(a0, a1, a2, a3, sab + j4 * 16);
        LDS128(c0, c1, c2, c3, scb + j4 * 16);
        float t[4];
        t[0] = fmaxf(fmaf(v.x, __uint_as_float(a0), __uint_as_float(c0)), 0.f);
        t[1] = fmaxf(fmaf(v.y, __uint_as_float(a1), __uint_as_float(c1)), 0.f);
        t[2] = fmaxf(fmaf(v.z, __uint_as_float(a2), __uint_as_float(c2)), 0.f);
        t[3] = fmaxf(fmaf(v.w, __uint_as_float(a3), __uint_as_float(c3)), 0.f);
        if (isA) {
#pragma unroll
            for (int e = 0; e < 4; e++) {
                int j = j4 * 4 + e;
                uint32_t w0, w1, w2, w3;
                LDS128(w0, w1, w2, w3, swa + j * 16);
                acc[0] = fmaf(t[e], __uint_as_float(w0), acc[0]);
                acc[1] = fmaf(t[e], __uint_as_float(w1), acc[1]);
                acc[2] = fmaf(t[e], __uint_as_float(w2), acc[2]);
            }
        } else {
#pragma unroll
            for (int e = 0; e < 4; e++) {
                int j = j4 * 4 + e;
                uint32_t w0, w1, w2, w3, w4;
                LDS128(w0, w1, w2, w3, swb + j * 32);
                LDS32(w4, swb + j * 32 + 16);
                acc[0] = fmaf(t[e], __uint_as_float(w0), acc[0]);
                acc[1] = fmaf(t[e], __uint_as_float(w1), acc[1]);
                acc[2] = fmaf(t[e], __uint_as_float(w2), acc[2]);
                acc[3] = fmaf(t[e], __uint_as_float(w3), acc[3]);
                acc[4] = fmaf(t[e], __uint_as_float(w4), acc[4]);
            }
        }
    }
#pragma unroll
    for (int off = 16; off > 0; off >>= 1) {
#pragma unroll
        for (int c = 0; c < 5; c++) acc[c] += __shfl_down_sync(0xFFFFFFFFu, acc[c], off);
    }
    if (lane == 0) {
        int C = isA ? 3 : 5;
        const float* bvec = isA ? ba : bb;
        int best = 0;
        float bestv = acc[0] + bvec[0];
#pragma unroll
        for (int c = 1; c < 5; c++) {
            if (c < C) {
                float lv = acc[c] + bvec[c];
                if (lv > bestv) { bestv = lv; best = c; }
            }
        }
        out[row] = (float)best;
    }
}

// ---------------------------------------------------------------------------
// launch  (5 kernels; all idempotent -> graph-safe)
// ---------------------------------------------------------------------------
extern "C" void kernel_launch(void* const* d_in, const int* in_sizes, int n_in,
                              void* d_out, int out_size) {
    const float* x     = (const float*)d_in[0];
    const float* W1    = (const float*)d_in[1];
    const float* b1    = (const float*)d_in[2];
    const float* gamma = (const float*)d_in[3];
    const float* beta  = (const float*)d_in[4];
    const float* Wa    = (const float*)d_in[5];
    const float* ba    = (const float*)d_in[6];
    const float* Wb    = (const float*)d_in[7];
    const float* bb    = (const float*)d_in[8];
    float* out = (float*)d_out;

    float* Hbuf;
    cudaGetSymbolAddress((void**)&Hbuf, g_h);

    cudaFuncSetAttribute(gemm_kernel, cudaFuncAttributeMaxDynamicSharedMemorySize,
                         SMEM_BYTES);

    splitX_kernel<<<(MDIM * KDIM / 4) / 256, 256>>>(x);
    splitB_kernel<<<1024, 256>>>(W1);

    dim3 ggrid(NDIM / TILE_N, MDIM / TILE_M);   // (4, 1024)
    gemm_kernel<<<ggrid, THREADS, SMEM_BYTES>>>(b1);

    finalize_kernel<<<NDIM / 8, 256>>>(gamma, beta);

    heads_kernel<<<(MDIM * 32) / 256, 256>>>(Hbuf, Wa, ba, Wb, bb, out);
}

// round 6
// speedup vs baseline: 1.0998x; 1.0998x over previous
#include <cuda_runtime.h>
#include <cuda_fp16.h>
#include <stdint.h>
#include <math.h>

// ---------------- problem constants ----------------
#define MDIM 131072   // B*N rows
#define KDIM 512      // D
#define NDIM 512      // H
#define NNODES 2048
#define HALFN 1024

#define TILE_M 128
#define TILE_N 128
#define KC 32
#define NCHUNK 16
#define THREADS 512
#define PITCH 80      // bytes per row in fp16 limb tiles (64 data + 16 pad)
#define XPITCH 144    // bytes per row in x fp32 stage (128 data + 16 pad)

// smem (bytes from 128-aligned dyn base), 3 stages:
//   A limbs: (s*2+p)*10240            s in 0..2, p in 0..1   -> 0..61440
//   B limbs: 61440 + (s*2+p)*10240                           -> ..122880
//   x fp32 : 122880 + s*18432                                -> ..178176
//   stat red: 178176 (2 x 2KB)
#define A_OFF(s, p) ((((s) * 2) + (p)) * 10240)
#define B_OFF(s, p) (61440 + (((s) * 2) + (p)) * 10240)
#define X_OFF(s)    (122880 + (s) * 18432)
#define SRED_S      178176
#define SRED_Q      180224
#define SMEM_BYTES  (182272 + 128)
#define HPITCH 132            // floats; epilogue staging (unions tile region)
#define SCALE_UP 4096.0f
#define SCALE_DN (1.0f / 4096.0f)

// ---------------- device scratch ----------------
__device__ float  g_h[(size_t)MDIM * NDIM];        // 256 MB hidden
__device__ float  g_ps[1024 * NDIM];               // per-CTA-row column sums
__device__ float  g_pq[1024 * NDIM];               // per-CTA-row column sumsq
__device__ float  g_a[NDIM];
__device__ float  g_c[NDIM];
__device__ __half g_Bh[KDIM * NDIM];               // W1^T limbs, [n][k]
__device__ __half g_Bm[KDIM * NDIM];               // scaled by 4096

// ---------------- PTX helpers ----------------
__device__ __forceinline__ uint32_t smem_u32(const void* p) {
    uint32_t a;
    asm("{ .reg .u64 t; cvta.to.shared.u64 t, %1; cvt.u32.u64 %0, t; }" : "=r"(a) : "l"(p));
    return a;
}
#define LDS128(r0, r1, r2, r3, addr) \
    asm volatile("ld.shared.v4.b32 {%0, %1, %2, %3}, [%4];" \
                 : "=r"(r0), "=r"(r1), "=r"(r2), "=r"(r3) : "r"(addr))
#define LDS32(r0, addr) \
    asm volatile("ld.shared.b32 %0, [%1];" : "=r"(r0) : "r"(addr))
#define STS128(r0, r1, r2, r3, addr) \
    asm volatile("st.shared.v4.b32 [%0], {%1, %2, %3, %4};" \
                 :: "r"(addr), "r"(r0), "r"(r1), "r"(r2), "r"(r3) : "memory")
#define STS64F(addr, x, y) \
    asm volatile("st.shared.v2.f32 [%0], {%1, %2};" :: "r"(addr), "f"(x), "f"(y) : "memory")
#define STS32F(addr, x) \
    asm volatile("st.shared.f32 [%0], %1;" :: "r"(addr), "f"(x) : "memory")

__device__ __forceinline__ void ldsm_x4(uint32_t* r, uint32_t addr) {
    asm volatile("ldmatrix.sync.aligned.m8n8.x4.shared.b16 {%0,%1,%2,%3}, [%4];"
                 : "=r"(r[0]), "=r"(r[1]), "=r"(r[2]), "=r"(r[3]) : "r"(addr));
}
__device__ __forceinline__ void mma16816(float* d, const uint32_t* a, const uint32_t* b) {
    asm volatile(
        "mma.sync.aligned.m16n8k16.row.col.f32.f16.f16.f32 "
        "{%0,%1,%2,%3}, {%4,%5,%6,%7}, {%8,%9}, {%0,%1,%2,%3};"
        : "+f"(d[0]), "+f"(d[1]), "+f"(d[2]), "+f"(d[3])
        : "r"(a[0]), "r"(a[1]), "r"(a[2]), "r"(a[3]), "r"(b[0]), "r"(b[1]));
}
__device__ __forceinline__ void cpasync16(uint32_t dst, const void* src) {
    asm volatile("cp.async.cg.shared.global [%0], [%1], 16;" :: "r"(dst), "l"(src));
}
#define CP_COMMIT() asm volatile("cp.async.commit_group;" ::: "memory")
#define CP_WAIT1()  asm volatile("cp.async.wait_group 1;" ::: "memory")
#define CP_WAIT0()  asm volatile("cp.async.wait_group 0;" ::: "memory")

// scaled fp16x2 split: v = h + m*2^-12 (m stored pre-scaled by 2^12)
__device__ __forceinline__ void split2(float v, uint32_t& h, uint32_t& m) {
    __half hh = __float2half_rn(v);
    float r = (v - __half2float(hh)) * SCALE_UP;
    __half hm = __float2half_rn(r);
    h = (uint32_t)__half_as_ushort(hh);
    m = (uint32_t)__half_as_ushort(hm);
}

// ---------------------------------------------------------------------------
// no-op padding kernels (align profiled launch slot onto the GEMM)
// ---------------------------------------------------------------------------
__global__ void noop_kernel() {}

// ---------------------------------------------------------------------------
// K1: split W1 [k][n] fp32 -> 2 fp16 matrices [n][k]
// ---------------------------------------------------------------------------
__global__ void __launch_bounds__(256) splitB_kernel(const float* __restrict__ W1) {
    int i = blockIdx.x * blockDim.x + threadIdx.x;   // i = k*512 + n
    int k = i >> 9, n = i & 511;
    uint32_t h, m;
    split2(W1[i], h, m);
    int o = n * KDIM + k;
    g_Bh[o] = __ushort_as_half((unsigned short)h);
    g_Bm[o] = __ushort_as_half((unsigned short)m);
}

// ---------------------------------------------------------------------------
// K2: fp16x2 HMMA GEMM  h = x @ W1 + b1, fused per-CTA column stats
// 512 threads, warp tile 32x32, 3-stage cp.async pipeline
// ---------------------------------------------------------------------------
__device__ __forceinline__ void issue_loads(const float* __restrict__ X, uint32_t base,
                                            int m0, int n0, int c, int tid) {
    const int s = c % 3;
    // x fp32: 128 rows x 128B; thread -> row tid>>2, 2 segs at (tid&3)*32B
    {
        int row = tid >> 2;
        int sb = (tid & 3) * 32;     // byte offset within row
        const float* src = X + (size_t)(m0 + row) * KDIM + c * KC + (sb >> 2);
        uint32_t dst = base + X_OFF(s) + row * XPITCH + sb;
        cpasync16(dst, src);
        cpasync16(dst + 16, src + 4);
    }
    // B limbs: 2 x (128 rows x 64B); thread -> limb tid>>8, row (tid>>1)&127, seg (tid&1)*2
    {
        int p = tid >> 8;
        int r = (tid >> 1) & 127;
        int sg = (tid & 1) * 32;
        const __half* gb = (p == 0) ? g_Bh : g_Bm;
        const __half* src = gb + (size_t)(n0 + r) * KDIM + c * KC + (sg >> 1);
        uint32_t dst = base + B_OFF(s, p) + r * PITCH + sg;
        cpasync16(dst, src);
        cpasync16(dst + 16, src + 8);
    }
    CP_COMMIT();
}

__device__ __forceinline__ void convert_x(uint32_t base, int c, int tid) {
    const int s = c % 3;
    int row = tid >> 2;
    int f = (tid & 3) * 8;           // 8 floats per thread (matches its own cp.asyncs)
    uint32_t xsrc = base + X_OFF(s) + row * XPITCH + f * 4;
    uint32_t ph[2], pm[2];
#pragma unroll
    for (int q = 0; q < 2; q++) {
        uint32_t u0, u1, u2, u3;
        LDS128(u0, u1, u2, u3, xsrc + q * 16);
        uint32_t h0, m0v, h1, m1v;
        split2(__uint_as_float(u0), h0, m0v);
        split2(__uint_as_float(u1), h1, m1v);
        ph[q] = h0 | (h1 << 16);
        pm[q] = m0v | (m1v << 16);
        split2(__uint_as_float(u2), h0, m0v);
        split2(__uint_as_float(u3), h1, m1v);
        uint32_t ph2 = h0 | (h1 << 16);
        uint32_t pm2 = m0v | (m1v << 16);
        if (q == 0) {
            uint32_t ro = (uint32_t)(row * PITCH + f * 2);
            // store first 4 halves per limb after both quads below; stash:
            ph[1] = ph2; pm[1] = pm2;   // overwritten next iter if q loop continued
        }
        if (q == 0) {
            // handled after loop via arrays; fallthrough
        }
        if (q == 0) { /* keep values */ } else { }
        if (q == 0) { ph[0] = ph[0]; }
        if (q == 1) { ph[1] = ph[1]; }
        // store both 16B groups at once at end of iteration q:
        if (q == 0) {
            // defer
        }
        (void)ph2; (void)pm2;
        if (q == 0) { /* second pair stored below via ph[1]/pm[1] trick */ }
    }
    // Recompute cleanly (compiler folds): do full 8-float convert in one pass
    {
        uint32_t u0, u1, u2, u3, v0, v1, v2, v3;
        LDS128(u0, u1, u2, u3, xsrc);
        LDS128(v0, v1, v2, v3, xsrc + 16);
        uint32_t h[8], m[8];
        split2(__uint_as_float(u0), h[0], m[0]);
        split2(__uint_as_float(u1), h[1], m[1]);
        split2(__uint_as_float(u2), h[2], m[2]);
        split2(__uint_as_float(u3), h[3], m[3]);
        split2(__uint_as_float(v0), h[4], m[4]);
        split2(__uint_as_float(v1), h[5], m[5]);
        split2(__uint_as_float(v2), h[6], m[6]);
        split2(__uint_as_float(v3), h[7], m[7]);
        uint32_t ro = (uint32_t)(row * PITCH + f * 2);
        STS128(h[0] | (h[1] << 16), h[2] | (h[3] << 16),
               h[4] | (h[5] << 16), h[6] | (h[7] << 16), base + A_OFF(s, 0) + ro);
        STS128(m[0] | (m[1] << 16), m[2] | (m[3] << 16),
               m[4] | (m[5] << 16), m[6] | (m[7] << 16), base + A_OFF(s, 1) + ro);
    }
}

__global__ void __launch_bounds__(THREADS, 1)
gemm_kernel(const float* __restrict__ X, const float* __restrict__ b1) {
    extern __shared__ char dyn[];
    __shared__ float sbias[TILE_N];

    const uint32_t base = (smem_u32(dyn) + 127u) & ~127u;
    const int tid = threadIdx.x;
    const int wid = tid >> 5;
    const int lane = tid & 31;
    const int m0 = blockIdx.y * TILE_M;
    const int n0 = blockIdx.x * TILE_N;

    if (tid < TILE_N) sbias[tid] = b1[n0 + tid];

    const int wm = (wid & 3) * 32;     // warp m-offset (4 positions)
    const int wn = (wid >> 2) * 32;    // warp n-offset (4 positions)

    float a1[2][4][4], a2[2][4][4];
#pragma unroll
    for (int i = 0; i < 2; i++)
#pragma unroll
        for (int j = 0; j < 4; j++)
#pragma unroll
            for (int q = 0; q < 4; q++) { a1[i][j][q] = 0.f; a2[i][j][q] = 0.f; }

    // prologue: load chunks 0 and 1, convert 0
    issue_loads(X, base, m0, n0, 0, tid);
    issue_loads(X, base, m0, n0, 1, tid);
    CP_WAIT1();
    convert_x(base, 0, tid);
    __syncthreads();

    // lane-constant ldsm address components
    const int arow = lane & 15;
    const int acolh = (lane >> 4) * 16;                 // bytes (k-half)
    const int bm = lane >> 3;                           // 0..3
    const int brow = ((bm & 2) << 2) + (lane & 7);      // n-row within 16
    const int bko = (bm & 1) * 16;                      // k-half bytes

    for (int c = 0; c < NCHUNK; c++) {
        const int s = c % 3;
        if (c + 2 < NCHUNK) issue_loads(X, base, m0, n0, c + 2, tid);
        if (c + 1 < NCHUNK) {
            CP_WAIT1();
            convert_x(base, c + 1, tid);
        }
        __syncthreads();

#pragma unroll
        for (int k16 = 0; k16 < 2; k16++) {
            const uint32_t koA = (uint32_t)(k16 * 32 + acolh);
            const uint32_t koB = (uint32_t)(k16 * 32 + bko);
            uint32_t aH[2][4], aM[2][4];
#pragma unroll
            for (int i = 0; i < 2; i++) {
                uint32_t ra = (uint32_t)((wm + i * 16 + arow) * PITCH);
                ldsm_x4(aH[i], base + A_OFF(s, 0) + ra + koA);
                ldsm_x4(aM[i], base + A_OFF(s, 1) + ra + koA);
            }
#pragma unroll
            for (int jj = 0; jj < 2; jj++) {
                uint32_t rb = (uint32_t)((wn + jj * 16 + brow) * PITCH) + koB;
                uint32_t bh[4], bmr[4];
                ldsm_x4(bh, base + B_OFF(s, 0) + rb);
                ldsm_x4(bmr, base + B_OFF(s, 1) + rb);
#pragma unroll
                for (int i = 0; i < 2; i++) {
                    mma16816(a1[i][jj * 2 + 0], aH[i], bh + 0);
                    mma16816(a1[i][jj * 2 + 1], aH[i], bh + 2);
                    mma16816(a2[i][jj * 2 + 0], aM[i], bh + 0);
                    mma16816(a2[i][jj * 2 + 1], aM[i], bh + 2);
                    mma16816(a2[i][jj * 2 + 0], aH[i], bmr + 0);
                    mma16816(a2[i][jj * 2 + 1], aH[i], bmr + 2);
                }
            }
        }
        __syncthreads();
    }

    // ---------------- epilogue: combine limbs, stage to smem ----------------
#pragma unroll
    for (int i = 0; i < 2; i++)
#pragma unroll
        for (int j = 0; j < 4; j++) {
            int r0 = wm + i * 16 + (lane >> 2);
            int c0 = wn + j * 8 + (lane & 3) * 2;
            float v0 = a1[i][j][0] + a2[i][j][0] * SCALE_DN;
            float v1 = a1[i][j][1] + a2[i][j][1] * SCALE_DN;
            float v2 = a1[i][j][2] + a2[i][j][2] * SCALE_DN;
            float v3 = a1[i][j][3] + a2[i][j][3] * SCALE_DN;
            STS64F(base + (uint32_t)((r0 * HPITCH + c0) * 4), v0, v1);
            STS64F(base + (uint32_t)(((r0 + 8) * HPITCH + c0) * 4), v2, v3);
        }
    __syncthreads();

    // coalesced global write with bias
#pragma unroll 4
    for (int t = 0; t < 8; t++) {
        int fidx = tid + t * THREADS;      // float4 index (4096 total)
        int r = fidx >> 5, cs = fidx & 31;
        uint32_t u0, u1, u2, u3;
        LDS128(u0, u1, u2, u3, base + (uint32_t)((r * HPITCH + cs * 4) * 4));
        float4 bv = *(const float4*)&sbias[cs * 4];
        float4 o;
        o.x = __uint_as_float(u0) + bv.x;
        o.y = __uint_as_float(u1) + bv.y;
        o.z = __uint_as_float(u2) + bv.z;
        o.w = __uint_as_float(u3) + bv.w;
        *(float4*)&g_h[(size_t)(m0 + r) * NDIM + n0 + cs * 4] = o;
    }

    // column stats: 4 threads per column, combine in smem -> 1 partial/col/CTA
    {
        int col = tid & 127;
        int q = tid >> 7;                  // 0..3 (row quarter)
        float bcolv = sbias[col];
        float ss = 0.f, s2 = 0.f;
#pragma unroll 8
        for (int r = q * 32; r < q * 32 + 32; r++) {
            uint32_t u;
            LDS32(u, base + (uint32_t)((r * HPITCH + col) * 4));
            float v = __uint_as_float(u) + bcolv;
            ss += v;
            s2 = fmaf(v, v, s2);
        }
        STS32F(base + SRED_S + (q * 128 + col) * 4, ss);
        STS32F(base + SRED_Q + (q * 128 + col) * 4, s2);
    }
    __syncthreads();
    if (tid < 128) {
        float ss = 0.f, s2 = 0.f;
#pragma unroll
        for (int q = 0; q < 4; q++) {
            uint32_t u, v;
            LDS32(u, base + SRED_S + (q * 128 + tid) * 4);
            LDS32(v, base + SRED_Q + (q * 128 + tid) * 4);
            ss += __uint_as_float(u);
            s2 += __uint_as_float(v);
        }
        int slot = blockIdx.y * NDIM + n0 + tid;
        g_ps[slot] = ss;
        g_pq[slot] = s2;
    }
}

// ---------------------------------------------------------------------------
// K3: finalize BN affine (one warp per column, fp64 reduce of 1024 partials)
// ---------------------------------------------------------------------------
__global__ void __launch_bounds__(256) finalize_kernel(const float* __restrict__ gamma,
                                                       const float* __restrict__ beta) {
    int col = blockIdx.x * 8 + (threadIdx.x >> 5);
    int lane = threadIdx.x & 31;
    double s = 0.0, q = 0.0;
    for (int i = lane; i < 1024; i += 32) {
        s += (double)g_ps[i * NDIM + col];
        q += (double)g_pq[i * NDIM + col];
    }
#pragma unroll
    for (int off = 16; off > 0; off >>= 1) {
        s += __shfl_down_sync(0xFFFFFFFFu, s, off);
        q += __shfl_down_sync(0xFFFFFFFFu, q, off);
    }
    if (lane == 0) {
        double mu = s / (double)MDIM;
        double var = q / (double)MDIM - mu * mu;
        double a = (double)gamma[col] / sqrt(var + 1e-5);
        g_a[col] = (float)a;
        g_c[col] = (float)((double)beta[col] - mu * a);
    }
}

// ---------------------------------------------------------------------------
// K4: heads (one warp per row; W, a, c staged in shared)
// ---------------------------------------------------------------------------
__global__ void __launch_bounds__(256) heads_kernel(const float* __restrict__ Hbuf,
                                                    const float* __restrict__ Wa,
                                                    const float* __restrict__ ba,
                                                    const float* __restrict__ Wb,
                                                    const float* __restrict__ bb,
                                                    float* __restrict__ out) {
    __shared__ float sWa[512 * 4];
    __shared__ float sWb[512 * 8];
    __shared__ float sa[512], sc[512];

    const int tid = threadIdx.x;
#pragma unroll
    for (int t = 0; t < 6; t++) {
        int i = tid + t * 256;
        sWa[(i / 3) * 4 + (i % 3)] = Wa[i];
    }
#pragma unroll
    for (int t = 0; t < 10; t++) {
        int i = tid + t * 256;
        sWb[(i / 5) * 8 + (i % 5)] = Wb[i];
    }
    {
        int i = tid * 2;
        sa[i] = g_a[i]; sa[i + 1] = g_a[i + 1];
        sc[i] = g_c[i]; sc[i + 1] = g_c[i + 1];
    }
    __syncthreads();

    const int row = (int)((blockIdx.x * blockDim.x + tid) >> 5);
    const int lane = tid & 31;
    const int n = row & (NNODES - 1);
    const bool isA = (n < HALFN);

    const float4* h4 = (const float4*)(Hbuf + (size_t)row * NDIM);
    const uint32_t sab = smem_u32(sa), scb = smem_u32(sc);
    const uint32_t swa = smem_u32(sWa), swb = smem_u32(sWb);

    float acc[5] = {0.f, 0.f, 0.f, 0.f, 0.f};

#pragma unroll
    for (int i = 0; i < 4; i++) {
        int j4 = i * 32 + lane;
        float4 v = h4[j4];
        uint32_t a0, a1, a2, a3, c0, c1, c2, c3;
        LDS128(a0, a1, a2, a3, sab + j4 * 16);
        LDS128(c0, c1, c2, c3, scb + j4 * 16);
        float t[4];
        t[0] = fmaxf(fmaf(v.x, __uint_as_float(a0), __uint_as_float(c0)), 0.f);
        t[1] = fmaxf(fmaf(v.y, __uint_as_float(a1), __uint_as_float(c1)), 0.f);
        t[2] = fmaxf(fmaf(v.z, __uint_as_float(a2), __uint_as_float(c2)), 0.f);
        t[3] = fmaxf(fmaf(v.w, __uint_as_float(a3), __uint_as_float(c3)), 0.f);
        if (isA) {
#pragma unroll
            for (int e = 0; e < 4; e++) {
                int j = j4 * 4 + e;
                uint32_t w0, w1, w2, w3;
                LDS128(w0, w1, w2, w3, swa + j * 16);
                acc[0] = fmaf(t[e], __uint_as_float(w0), acc[0]);
                acc[1] = fmaf(t[e], __uint_as_float(w1), acc[1]);
                acc[2] = fmaf(t[e], __uint_as_float(w2), acc[2]);
            }
        } else {
#pragma unroll
            for (int e = 0; e < 4; e++) {
                int j = j4 * 4 + e;
                uint32_t w0, w1, w2, w3, w4;
                LDS128(w0, w1, w2, w3, swb + j * 32);
                LDS32(w4, swb + j * 32 + 16);
                acc[0] = fmaf(t[e], __uint_as_float(w0), acc[0]);
                acc[1] = fmaf(t[e], __uint_as_float(w1), acc[1]);
                acc[2] = fmaf(t[e], __uint_as_float(w2), acc[2]);
                acc[3] = fmaf(t[e], __uint_as_float(w3), acc[3]);
                acc[4] = fmaf(t[e], __uint_as_float(w4), acc[4]);
            }
        }
    }
#pragma unroll
    for (int off = 16; off > 0; off >>= 1) {
#pragma unroll
        for (int c = 0; c < 5; c++) acc[c] += __shfl_down_sync(0xFFFFFFFFu, acc[c], off);
    }
    if (lane == 0) {
        int C = isA ? 3 : 5;
        const float* bvec = isA ? ba : bb;
        int best = 0;
        float bestv = acc[0] + bvec[0];
#pragma unroll
        for (int c = 1; c < 5; c++) {
            if (c < C) {
                float lv = acc[c] + bvec[c];
                if (lv > bestv) { bestv = lv; best = c; }
            }
        }
        out[row] = (float)best;
    }
}

// ---------------------------------------------------------------------------
// launch — GEMM placed 4th so the profiler slot lands on it
// ---------------------------------------------------------------------------
extern "C" void kernel_launch(void* const* d_in, const int* in_sizes, int n_in,
                              void* d_out, int out_size) {
    const float* x     = (const float*)d_in[0];
    const float* W1    = (const float*)d_in[1];
    const float* b1    = (const float*)d_in[2];
    const float* gamma = (const float*)d_in[3];
    const float* beta  = (const float*)d_in[4];
    const float* Wa    = (const float*)d_in[5];
    const float* ba    = (const float*)d_in[6];
    const float* Wb    = (const float*)d_in[7];
    const float* bb    = (const float*)d_in[8];
    float* out = (float*)d_out;

    float* Hbuf;
    cudaGetSymbolAddress((void**)&Hbuf, g_h);

    cudaFuncSetAttribute(gemm_kernel, cudaFuncAttributeMaxDynamicSharedMemorySize,
                         SMEM_BYTES);

    splitB_kernel<<<1024, 256>>>(W1);
    noop_kernel<<<1, 32>>>();
    noop_kernel<<<1, 32>>>();

    dim3 ggrid(NDIM / TILE_N, MDIM / TILE_M);   // (4, 1024)
    gemm_kernel<<<ggrid, THREADS, SMEM_BYTES>>>(x, b1);

    finalize_kernel<<<NDIM / 8, 256>>>(gamma, beta);

    heads_kernel<<<(MDIM * 32) / 256, 256>>>(Hbuf, Wa, ba, Wb, bb, out);
}

// round 7
// speedup vs baseline: 1.6977x; 1.5437x over previous
#include <cuda_runtime.h>
#include <cuda_fp16.h>
#include <stdint.h>
#include <math.h>

// ---------------- problem constants ----------------
#define MDIM 131072   // B*N rows
#define KDIM 512      // D
#define NDIM 512      // H
#define NNODES 2048
#define HALFN 1024

#define TILE_M 128
#define TILE_N 128
#define KC 32
#define NCHUNK 16
#define THREADS 512
#define PITCH 80      // bytes per row in fp16 limb tiles (64 data + 16 pad)

// smem (bytes from 128-aligned dyn base), 3 stages:
//   A limbs: (s*2+p)*10240     -> 0..61440
//   B limbs: 61440 + (s*2+p)*10240 -> ..122880
//   stat red: 122880 (2 x 2KB)
#define A_OFF(s, p) ((((s) * 2) + (p)) * 10240)
#define B_OFF(s, p) (61440 + (((s) * 2) + (p)) * 10240)
#define SRED_S      122880
#define SRED_Q      124928
#define SMEM_BYTES  (126976 + 128)
#define HPITCH 132            // floats; epilogue staging (reuses tile region)
#define SCALE_UP 4096.0f
#define SCALE_DN (1.0f / 4096.0f)

// ---------------- device scratch ----------------
__device__ float  g_h[(size_t)MDIM * NDIM];        // 256 MB hidden
__device__ float  g_ps[1024 * NDIM];               // per-CTA-row column sums
__device__ float  g_pq[1024 * NDIM];               // per-CTA-row column sumsq
__device__ float  g_a[NDIM];
__device__ float  g_c[NDIM];
__device__ __half g_Bh[KDIM * NDIM];               // W1^T limbs, [n][k]
__device__ __half g_Bm[KDIM * NDIM];               // scaled by 4096

// ---------------- PTX helpers ----------------
__device__ __forceinline__ uint32_t smem_u32(const void* p) {
    uint32_t a;
    asm("{ .reg .u64 t; cvta.to.shared.u64 t, %1; cvt.u32.u64 %0, t; }" : "=r"(a) : "l"(p));
    return a;
}
#define LDS128(r0, r1, r2, r3, addr) \
    asm volatile("ld.shared.v4.b32 {%0, %1, %2, %3}, [%4];" \
                 : "=r"(r0), "=r"(r1), "=r"(r2), "=r"(r3) : "r"(addr))
#define LDS32(r0, addr) \
    asm volatile("ld.shared.b32 %0, [%1];" : "=r"(r0) : "r"(addr))
#define STS128(r0, r1, r2, r3, addr) \
    asm volatile("st.shared.v4.b32 [%0], {%1, %2, %3, %4};" \
                 :: "r"(addr), "r"(r0), "r"(r1), "r"(r2), "r"(r3) : "memory")
#define STS64F(addr, x, y) \
    asm volatile("st.shared.v2.f32 [%0], {%1, %2};" :: "r"(addr), "f"(x), "f"(y) : "memory")
#define STS32F(addr, x) \
    asm volatile("st.shared.f32 [%0], %1;" :: "r"(addr), "f"(x) : "memory")

__device__ __forceinline__ void ldsm_x4(uint32_t* r, uint32_t addr) {
    asm volatile("ldmatrix.sync.aligned.m8n8.x4.shared.b16 {%0,%1,%2,%3}, [%4];"
                 : "=r"(r[0]), "=r"(r[1]), "=r"(r[2]), "=r"(r[3]) : "r"(addr));
}
__device__ __forceinline__ void mma16816(float* d, const uint32_t* a, const uint32_t* b) {
    asm volatile(
        "mma.sync.aligned.m16n8k16.row.col.f32.f16.f16.f32 "
        "{%0,%1,%2,%3}, {%4,%5,%6,%7}, {%8,%9}, {%0,%1,%2,%3};"
        : "+f"(d[0]), "+f"(d[1]), "+f"(d[2]), "+f"(d[3])
        : "r"(a[0]), "r"(a[1]), "r"(a[2]), "r"(a[3]), "r"(b[0]), "r"(b[1]));
}
__device__ __forceinline__ void cpasync16(uint32_t dst, const void* src) {
    asm volatile("cp.async.cg.shared.global [%0], [%1], 16;" :: "r"(dst), "l"(src));
}
#define CP_COMMIT() asm volatile("cp.async.commit_group;" ::: "memory")
#define CP_WAIT1()  asm volatile("cp.async.wait_group 1;" ::: "memory")
#define CP_WAIT0()  asm volatile("cp.async.wait_group 0;" ::: "memory")

// scaled fp16x2 split: v = h + m*2^-12 (m stored pre-scaled by 2^12)
__device__ __forceinline__ void split2(float v, uint32_t& h, uint32_t& m) {
    __half hh = __float2half_rn(v);
    float r = (v - __half2float(hh)) * SCALE_UP;
    __half hm = __float2half_rn(r);
    h = (uint32_t)__half_as_ushort(hh);
    m = (uint32_t)__half_as_ushort(hm);
}

// ---------------------------------------------------------------------------
// no-op padding kernels (keep profiled launch slot on the GEMM)
// ---------------------------------------------------------------------------
__global__ void noop_kernel() {}

// ---------------------------------------------------------------------------
// K1: split W1 [k][n] fp32 -> 2 fp16 matrices [n][k]
// ---------------------------------------------------------------------------
__global__ void __launch_bounds__(256) splitB_kernel(const float* __restrict__ W1) {
    int i = blockIdx.x * blockDim.x + threadIdx.x;   // i = k*512 + n
    int k = i >> 9, n = i & 511;
    uint32_t h, m;
    split2(W1[i], h, m);
    int o = n * KDIM + k;
    g_Bh[o] = __ushort_as_half((unsigned short)h);
    g_Bm[o] = __ushort_as_half((unsigned short)m);
}

// ---------------------------------------------------------------------------
// K2: fp16x2 HMMA GEMM  h = x @ W1 + b1, fused per-CTA column stats
// 512 threads, warp tile 32x32, register-side x split, 1 sync/chunk
// ---------------------------------------------------------------------------
__device__ __forceinline__ void issue_B(uint32_t base, int n0, int c, int tid) {
    const int s = c % 3;
    int p = tid >> 8;
    int r = (tid >> 1) & 127;
    int sg = (tid & 1) * 32;
    const __half* gb = (p == 0) ? g_Bh : g_Bm;
    const __half* src = gb + (size_t)(n0 + r) * KDIM + c * KC + (sg >> 1);
    uint32_t dst = base + B_OFF(s, p) + r * PITCH + sg;
    cpasync16(dst, src);
    cpasync16(dst + 16, src + 8);
    CP_COMMIT();
}

__device__ __forceinline__ void ldg_x(const float* __restrict__ X, int m0, int c,
                                      int xrow, int xf, float4& xa, float4& xb) {
    const float4* src = (const float4*)(X + (size_t)(m0 + xrow) * KDIM + c * KC + xf);
    xa = src[0];
    xb = src[1];
}

__device__ __forceinline__ void convert_sts(uint32_t base, int c, int xrow, int xf,
                                            const float4& xa, const float4& xb) {
    const int s = c % 3;
    uint32_t h[8], m[8];
    split2(xa.x, h[0], m[0]);
    split2(xa.y, h[1], m[1]);
    split2(xa.z, h[2], m[2]);
    split2(xa.w, h[3], m[3]);
    split2(xb.x, h[4], m[4]);
    split2(xb.y, h[5], m[5]);
    split2(xb.z, h[6], m[6]);
    split2(xb.w, h[7], m[7]);
    uint32_t ro = (uint32_t)(xrow * PITCH + xf * 2);
    STS128(h[0] | (h[1] << 16), h[2] | (h[3] << 16),
           h[4] | (h[5] << 16), h[6] | (h[7] << 16), base + A_OFF(s, 0) + ro);
    STS128(m[0] | (m[1] << 16), m[2] | (m[3] << 16),
           m[4] | (m[5] << 16), m[6] | (m[7] << 16), base + A_OFF(s, 1) + ro);
}

__global__ void __launch_bounds__(THREADS, 1)
gemm_kernel(const float* __restrict__ X, const float* __restrict__ b1) {
    extern __shared__ char dyn[];
    __shared__ float sbias[TILE_N];

    const uint32_t base = (smem_u32(dyn) + 127u) & ~127u;
    const int tid = threadIdx.x;
    const int wid = tid >> 5;
    const int lane = tid & 31;
    const int m0 = blockIdx.y * TILE_M;
    const int n0 = blockIdx.x * TILE_N;

    if (tid < TILE_N) sbias[tid] = b1[n0 + tid];

    const int wm = (wid & 3) * 32;
    const int wn = (wid >> 2) * 32;
    const int xrow = tid >> 2;
    const int xf = (tid & 3) * 8;

    float a1[2][4][4], a2[2][4][4];
#pragma unroll
    for (int i = 0; i < 2; i++)
#pragma unroll
        for (int j = 0; j < 4; j++)
#pragma unroll
            for (int q = 0; q < 4; q++) { a1[i][j][q] = 0.f; a2[i][j][q] = 0.f; }

    // prologue: chunks 0 and 1
    {
        float4 xa, xb;
        issue_B(base, n0, 0, tid);
        issue_B(base, n0, 1, tid);
        ldg_x(X, m0, 0, xrow, xf, xa, xb);
        convert_sts(base, 0, xrow, xf, xa, xb);
        ldg_x(X, m0, 1, xrow, xf, xa, xb);
        convert_sts(base, 1, xrow, xf, xa, xb);
        CP_WAIT1();   // B(0) complete
        __syncthreads();
    }

    // lane-constant ldsm address components
    const int arow = lane & 15;
    const int acolh = (lane >> 4) * 16;
    const int bm = lane >> 3;
    const int brow = ((bm & 2) << 2) + (lane & 7);
    const int bko = (bm & 1) * 16;

    for (int c = 0; c < NCHUNK; c++) {
        const int s = c % 3;
        float4 xa, xb;
        const bool pre = (c + 2 < NCHUNK);
        if (pre) {
            ldg_x(X, m0, c + 2, xrow, xf, xa, xb);   // latency hidden under MMA
            issue_B(base, n0, c + 2, tid);
        }

#pragma unroll
        for (int k16 = 0; k16 < 2; k16++) {
            const uint32_t koA = (uint32_t)(k16 * 32 + acolh);
            const uint32_t koB = (uint32_t)(k16 * 32 + bko);
            uint32_t aH[2][4], aM[2][4];
#pragma unroll
            for (int i = 0; i < 2; i++) {
                uint32_t ra = (uint32_t)((wm + i * 16 + arow) * PITCH);
                ldsm_x4(aH[i], base + A_OFF(s, 0) + ra + koA);
                ldsm_x4(aM[i], base + A_OFF(s, 1) + ra + koA);
            }
#pragma unroll
            for (int jj = 0; jj < 2; jj++) {
                uint32_t rb = (uint32_t)((wn + jj * 16 + brow) * PITCH) + koB;
                uint32_t bh[4], bmr[4];
                ldsm_x4(bh, base + B_OFF(s, 0) + rb);
                ldsm_x4(bmr, base + B_OFF(s, 1) + rb);
#pragma unroll
                for (int i = 0; i < 2; i++) {
                    mma16816(a1[i][jj * 2 + 0], aH[i], bh + 0);
                    mma16816(a1[i][jj * 2 + 1], aH[i], bh + 2);
                    mma16816(a2[i][jj * 2 + 0], aM[i], bh + 0);
                    mma16816(a2[i][jj * 2 + 1], aM[i], bh + 2);
                    mma16816(a2[i][jj * 2 + 0], aH[i], bmr + 0);
                    mma16816(a2[i][jj * 2 + 1], aH[i], bmr + 2);
                }
            }
        }

        if (pre) {
            convert_sts(base, c + 2, xrow, xf, xa, xb);
            CP_WAIT1();          // B(c+1) complete
        } else if (c + 1 < NCHUNK) {
            CP_WAIT0();          // last pending B group
        }
        if (c + 1 < NCHUNK) __syncthreads();
    }

    // ---------------- epilogue: combine limbs, stage to smem ----------------
    __syncthreads();
#pragma unroll
    for (int i = 0; i < 2; i++)
#pragma unroll
        for (int j = 0; j < 4; j++) {
            int r0 = wm + i * 16 + (lane >> 2);
            int c0 = wn + j * 8 + (lane & 3) * 2;
            float v0 = a1[i][j][0] + a2[i][j][0] * SCALE_DN;
            float v1 = a1[i][j][1] + a2[i][j][1] * SCALE_DN;
            float v2 = a1[i][j][2] + a2[i][j][2] * SCALE_DN;
            float v3 = a1[i][j][3] + a2[i][j][3] * SCALE_DN;
            STS64F(base + (uint32_t)((r0 * HPITCH + c0) * 4), v0, v1);
            STS64F(base + (uint32_t)(((r0 + 8) * HPITCH + c0) * 4), v2, v3);
        }
    __syncthreads();

    // coalesced global write with bias
#pragma unroll 4
    for (int t = 0; t < 8; t++) {
        int fidx = tid + t * THREADS;
        int r = fidx >> 5, cs = fidx & 31;
        uint32_t u0, u1, u2, u3;
        LDS128(u0, u1, u2, u3, base + (uint32_t)((r * HPITCH + cs * 4) * 4));
        float4 bv = *(const float4*)&sbias[cs * 4];
        float4 o;
        o.x = __uint_as_float(u0) + bv.x;
        o.y = __uint_as_float(u1) + bv.y;
        o.z = __uint_as_float(u2) + bv.z;
        o.w = __uint_as_float(u3) + bv.w;
        *(float4*)&g_h[(size_t)(m0 + r) * NDIM + n0 + cs * 4] = o;
    }

    // column stats: 4 threads per column -> smem combine -> 1 partial/col/CTA
    {
        int col = tid & 127;
        int q = tid >> 7;
        float bcolv = sbias[col];
        float ss = 0.f, s2 = 0.f;
#pragma unroll 8
        for (int r = q * 32; r < q * 32 + 32; r++) {
            uint32_t u;
            LDS32(u, base + (uint32_t)((r * HPITCH + col) * 4));
            float v = __uint_as_float(u) + bcolv;
            ss += v;
            s2 = fmaf(v, v, s2);
        }
        STS32F(base + SRED_S + (q * 128 + col) * 4, ss);
        STS32F(base + SRED_Q + (q * 128 + col) * 4, s2);
    }
    __syncthreads();
    if (tid < 128) {
        float ss = 0.f, s2 = 0.f;
#pragma unroll
        for (int q = 0; q < 4; q++) {
            uint32_t u, v;
            LDS32(u, base + SRED_S + (q * 128 + tid) * 4);
            LDS32(v, base + SRED_Q + (q * 128 + tid) * 4);
            ss += __uint_as_float(u);
            s2 += __uint_as_float(v);
        }
        int slot = blockIdx.y * NDIM + n0 + tid;
        g_ps[slot] = ss;
        g_pq[slot] = s2;
    }
}

// ---------------------------------------------------------------------------
// K3: finalize BN affine (one warp per column, fp64 reduce of 1024 partials)
// ---------------------------------------------------------------------------
__global__ void __launch_bounds__(256) finalize_kernel(const float* __restrict__ gamma,
                                                       const float* __restrict__ beta) {
    int col = blockIdx.x * 8 + (threadIdx.x >> 5);
    int lane = threadIdx.x & 31;
    double s = 0.0, q = 0.0;
    for (int i = lane; i < 1024; i += 32) {
        s += (double)g_ps[i * NDIM + col];
        q += (double)g_pq[i * NDIM + col];
    }
#pragma unroll
    for (int off = 16; off > 0; off >>= 1) {
        s += __shfl_down_sync(0xFFFFFFFFu, s, off);
        q += __shfl_down_sync(0xFFFFFFFFu, q, off);
    }
    if (lane == 0) {
        double mu = s / (double)MDIM;
        double var = q / (double)MDIM - mu * mu;
        double a = (double)gamma[col] / sqrt(var + 1e-5);
        g_a[col] = (float)a;
        g_c[col] = (float)((double)beta[col] - mu * a);
    }
}

// ---------------------------------------------------------------------------
// K4: heads (one warp per row; vectorized float4 weight loads, no smem)
// ---------------------------------------------------------------------------
__global__ void __launch_bounds__(256) heads_kernel(const float* __restrict__ Hbuf,
                                                    const float* __restrict__ Wa,
                                                    const float* __restrict__ ba,
                                                    const float* __restrict__ Wb,
                                                    const float* __restrict__ bb,
                                                    float* __restrict__ out) {
    const int row = (int)((blockIdx.x * blockDim.x + threadIdx.x) >> 5);
    const int lane = threadIdx.x & 31;
    const int n = row & (NNODES - 1);
    const bool isA = (n < HALFN);

    const float4* h4 = (const float4*)(Hbuf + (size_t)row * NDIM);
    const float4* ga4 = (const float4*)g_a;
    const float4* gc4 = (const float4*)g_c;
    const float4* wa4 = (const float4*)Wa;   // rows of 3 -> 12 floats per 4 j's
    const float4* wb4 = (const float4*)Wb;   // rows of 5 -> 20 floats per 4 j's

    float acc[5] = {0.f, 0.f, 0.f, 0.f, 0.f};

#pragma unroll
    for (int i = 0; i < 4; i++) {
        int j4 = i * 32 + lane;               // group of 4 h-columns
        float4 v = h4[j4];
        float4 av = ga4[j4];
        float4 cv = gc4[j4];
        float t0 = fmaxf(fmaf(v.x, av.x, cv.x), 0.f);
        float t1 = fmaxf(fmaf(v.y, av.y, cv.y), 0.f);
        float t2 = fmaxf(fmaf(v.z, av.z, cv.z), 0.f);
        float t3 = fmaxf(fmaf(v.w, av.w, cv.w), 0.f);
        if (isA) {
            float4 w0 = wa4[j4 * 3 + 0];
            float4 w1 = wa4[j4 * 3 + 1];
            float4 w2 = wa4[j4 * 3 + 2];
            acc[0] = fmaf(t0, w0.x, acc[0]);
            acc[1] = fmaf(t0, w0.y, acc[1]);
            acc[2] = fmaf(t0, w0.z, acc[2]);
            acc[0] = fmaf(t1, w0.w, acc[0]);
            acc[1] = fmaf(t1, w1.x, acc[1]);
            acc[2] = fmaf(t1, w1.y, acc[2]);
            acc[0] = fmaf(t2, w1.z, acc[0]);
            acc[1] = fmaf(t2, w1.w, acc[1]);
            acc[2] = fmaf(t2, w2.x, acc[2]);
            acc[0] = fmaf(t3, w2.y, acc[0]);
            acc[1] = fmaf(t3, w2.z, acc[1]);
            acc[2] = fmaf(t3, w2.w, acc[2]);
        } else {
            float4 w0 = wb4[j4 * 5 + 0];
            float4 w1 = wb4[j4 * 5 + 1];
            float4 w2 = wb4[j4 * 5 + 2];
            float4 w3 = wb4[j4 * 5 + 3];
            float4 w4 = wb4[j4 * 5 + 4];
            acc[0] = fmaf(t0, w0.x, acc[0]);
            acc[1] = fmaf(t0, w0.y, acc[1]);
            acc[2] = fmaf(t0, w0.z, acc[2]);
            acc[3] = fmaf(t0, w0.w, acc[3]);
            acc[4] = fmaf(t0, w1.x, acc[4]);
            acc[0] = fmaf(t1, w1.y, acc[0]);
            acc[1] = fmaf(t1, w1.z, acc[1]);
            acc[2] = fmaf(t1, w1.w, acc[2]);
            acc[3] = fmaf(t1, w2.x, acc[3]);
            acc[4] = fmaf(t1, w2.y, acc[4]);
            acc[0] = fmaf(t2, w2.z, acc[0]);
            acc[1] = fmaf(t2, w2.w, acc[1]);
            acc[2] = fmaf(t2, w3.x, acc[2]);
            acc[3] = fmaf(t2, w3.y, acc[3]);
            acc[4] = fmaf(t2, w3.z, acc[4]);
            acc[0] = fmaf(t3, w3.w, acc[0]);
            acc[1] = fmaf(t3, w4.x, acc[1]);
            acc[2] = fmaf(t3, w4.y, acc[2]);
            acc[3] = fmaf(t3, w4.z, acc[3]);
            acc[4] = fmaf(t3, w4.w, acc[4]);
        }
    }
#pragma unroll
    for (int off = 16; off > 0; off >>= 1) {
#pragma unroll
        for (int c = 0; c < 5; c++) acc[c] += __shfl_down_sync(0xFFFFFFFFu, acc[c], off);
    }
    if (lane == 0) {
        int C = isA ? 3 : 5;
        const float* bvec = isA ? ba : bb;
        int best = 0;
        float bestv = acc[0] + bvec[0];
#pragma unroll
        for (int c = 1; c < 5; c++) {
            if (c < C) {
                float lv = acc[c] + bvec[c];
                if (lv > bestv) { bestv = lv; best = c; }
            }
        }
        out[row] = (float)best;
    }
}

// ---------------------------------------------------------------------------
// launch — GEMM kept in the 4th slot for profiling
// ---------------------------------------------------------------------------
extern "C" void kernel_launch(void* const* d_in, const int* in_sizes, int n_in,
                              void* d_out, int out_size) {
    const float* x     = (const float*)d_in[0];
    const float* W1    = (const float*)d_in[1];
    const float* b1    = (const float*)d_in[2];
    const float* gamma = (const float*)d_in[3];
    const float* beta  = (const float*)d_in[4];
    const float* Wa    = (const float*)d_in[5];
    const float* ba    = (const float*)d_in[6];
    const float* Wb    = (const float*)d_in[7];
    const float* bb    = (const float*)d_in[8];
    float* out = (float*)d_out;

    float* Hbuf;
    cudaGetSymbolAddress((void**)&Hbuf, g_h);

    cudaFuncSetAttribute(gemm_kernel, cudaFuncAttributeMaxDynamicSharedMemorySize,
                         SMEM_BYTES);

    splitB_kernel<<<1024, 256>>>(W1);
    noop_kernel<<<1, 32>>>();
    noop_kernel<<<1, 32>>>();

    dim3 ggrid(NDIM / TILE_N, MDIM / TILE_M);   // (4, 1024)
    gemm_kernel<<<ggrid, THREADS, SMEM_BYTES>>>(x, b1);

    finalize_kernel<<<NDIM / 8, 256>>>(gamma, beta);

    heads_kernel<<<(MDIM * 32) / 256, 256>>>(Hbuf, Wa, ba, Wb, bb, out);
}